// round 16
// baseline (speedup 1.0000x reference)
#include <cuda_runtime.h>
#include <cuda_bf16.h>
#include <cstdint>

// Problem constants
#define BATCH 512
#define CIN   3
#define HIMG  256
#define DIN   9216
#define HG    1024
#define HL    128
#define NOUT  1152

#define SPLIT1 8       // GEMM1 K-splits (9216/8 = 1152)
#define SPLIT2 4       // GEMM2 K-splits (1024/4 = 256)

// Scratch
__device__ float g_glimpse[BATCH * DIN];
__device__ float g_h[BATCH * HG];
__device__ float g_hw[BATCH * HL];
__device__ float g_part1[SPLIT1][BATCH * HG];
__device__ float g_part2[SPLIT2][BATCH * NOUT];

// ---------------------------------------------------------------------------
// Foveation (hierarchical) + fused "where" path. (proven R15)
// ---------------------------------------------------------------------------
__global__ __launch_bounds__(256)
void foveate2_kernel(const float* __restrict__ x,
                     const float* __restrict__ l,
                     const float* __restrict__ W2,
                     const float* __restrict__ b2)
{
    __shared__ float p1[64 * 64];

    const int bid = blockIdx.x;
    const int tid = threadIdx.x;

    if (bid >= BATCH * CIN) {
        int base = ((bid - BATCH * CIN) * 256 + tid) * 4;
        int b = base / HL;
        int n = base % HL;
        float l0 = l[2 * b + 0];
        float l1 = l[2 * b + 1];
        float4 bb = *(const float4*)&b2[n];
        float4 w0 = *(const float4*)&W2[2 * n];
        float4 w1 = *(const float4*)&W2[2 * n + 4];
        float4 v;
        v.x = fmaxf(bb.x + l0 * w0.x + l1 * w0.y, 0.0f);
        v.y = fmaxf(bb.y + l0 * w0.z + l1 * w0.w, 0.0f);
        v.z = fmaxf(bb.z + l0 * w1.x + l1 * w1.y, 0.0f);
        v.w = fmaxf(bb.w + l0 * w1.z + l1 * w1.w, 0.0f);
        *(float4*)&g_hw[base] = v;
        return;
    }

    const int b = bid / 3;
    const int c = bid - 3 * b;

    float l0 = l[2 * b + 0];
    float l1 = l[2 * b + 1];
    int fx = (int)floorf(0.5f * ((l0 + 1.0f) * 256.0f));
    int fy = (int)floorf(0.5f * ((l1 + 1.0f) * 256.0f));
    fx = min(max(fx, 0), 256);
    fy = min(max(fy, 0), 256);

    const int y0 = fy - 64;
    const int x0 = fx - 64;

    const float* __restrict__ src = x + ((long long)b * CIN + c) * (HIMG * HIMG);
    float* __restrict__ gout = g_glimpse + (long long)b * DIN + c * 1024;

    #pragma unroll
    for (int i = 0; i < 16; ++i) {
        int q  = tid + 256 * i;
        int qy = q >> 6;
        int qx = q & 63;
        int yb = y0 + 2 * qy;
        int xb = x0 + 2 * qx;

        float v00 = 0.0f, v01 = 0.0f, v10 = 0.0f, v11 = 0.0f;
        bool xi0 = (unsigned)xb < 256u;
        bool xi1 = (unsigned)(xb + 1) < 256u;
        if ((unsigned)yb < 256u) {
            const float* r = src + yb * HIMG;
            if (xi0) v00 = r[xb];
            if (xi1) v01 = r[xb + 1];
        }
        if ((unsigned)(yb + 1) < 256u) {
            const float* r = src + (yb + 1) * HIMG;
            if (xi0) v10 = r[xb];
            if (xi1) v11 = r[xb + 1];
        }
        p1[q] = v00 + v01 + v10 + v11;

        if (qy >= 24 && qy < 40 && qx >= 24 && qx < 40) {
            int i0 = 2 * qy - 48;
            int j0 = 2 * qx - 48;
            gout[i0 * 32 + j0]           = v00;
            gout[i0 * 32 + j0 + 1]       = v01;
            gout[(i0 + 1) * 32 + j0]     = v10;
            gout[(i0 + 1) * 32 + j0 + 1] = v11;
        }
    }
    __syncthreads();

    #pragma unroll
    for (int i = 0; i < 4; ++i) {
        int o  = tid + 256 * i;
        int oi = o >> 5;
        int oj = o & 31;
        gout[3072 + o] = p1[(16 + oi) * 64 + (16 + oj)] * 0.25f;
        float s = p1[(2 * oi) * 64 + 2 * oj]
                + p1[(2 * oi) * 64 + 2 * oj + 1]
                + p1[(2 * oi + 1) * 64 + 2 * oj]
                + p1[(2 * oi + 1) * 64 + 2 * oj + 1];
        gout[6144 + o] = s * 0.0625f;
    }
}

// ---------------------------------------------------------------------------
// TF32 machinery
// ---------------------------------------------------------------------------
__device__ __forceinline__ uint32_t f2tf32(float f) {
    uint32_t u;
    asm("cvt.rna.tf32.f32 %0, %1;" : "=r"(u) : "f"(f));
    return u;
}

__device__ __forceinline__ void mma_tf32(float c[4],
                                         const uint32_t a[4],
                                         const uint32_t b[2]) {
    asm volatile(
        "mma.sync.aligned.m16n8k8.row.col.f32.tf32.tf32.f32 "
        "{%0,%1,%2,%3}, {%4,%5,%6,%7}, {%8,%9}, {%0,%1,%2,%3};"
        : "+f"(c[0]), "+f"(c[1]), "+f"(c[2]), "+f"(c[3])
        : "r"(a[0]), "r"(a[1]), "r"(a[2]), "r"(a[3]),
          "r"(b[0]), "r"(b[1]));
}

// ===========================================================================
// Fragment-packed GEMM, BK=16, generic over warp layout.
//   MFRAG: 16-row m-fragments per warp;  NFRAG: 8-col n-fragments per warp
//   WMG x WNG warps.  BM = WMG*MFRAG*16 == BN = WNG*NFRAG*8 (required).
// Smem A layout (words): (ks*4 + t)*TSA + ((wmi*MFRAG+mf)*8 + g)*4 + h*2 + j
//   holding A[k0 + ks*8 + t + 4h][m0 + wmi*MFRAG*16 + mf*16 + g + 8j]
// Smem B layout (words): (ks*4 + t)*TSB + ((wni*NFRAG+nf)*8 + g)*2 + h
// TSA,TSB ≡ 8 (mod 32) for conflict-free consumer loads.
// ===========================================================================
template<int MFRAG, int NFRAG, int WMG, int WNG, int TSA, int TSB>
__device__ __forceinline__ void gemm_frag_phase(
    const float* __restrict__ A, int lda,
    const float* __restrict__ W, int ldw,
    int K, int m0, int n0,
    uint32_t* __restrict__ sA,   // 2 * 8*TSA words
    uint32_t* __restrict__ sB,   // 2 * 8*TSB words
    float acc[MFRAG][NFRAG][4])
{
    const int NT   = 32 * WMG * WNG;
    const int tid  = threadIdx.x;
    const int lane = tid & 31;
    const int warp = tid >> 5;
    const int wmi  = warp / WNG;
    const int wni  = warp % WNG;
    const int g    = lane >> 2;
    const int t    = lane & 3;

    const int ABUF = 8 * TSA;
    const int BBUF = 8 * TSB;

    // producer coords (2 float4 each for A and B per slab)
    int rowi[2], ki[2], baseA[2], baseB[2];
    #pragma unroll
    for (int i = 0; i < 2; ++i) {
        int idx = tid + NT * i;
        rowi[i] = idx >> 2;          // 0..BM-1
        ki[i]   = (idx & 3) * 4;     // 0,4,8,12
        int ks = ki[i] >> 3;
        int h  = (ki[i] >> 2) & 1;
        int m  = rowi[i];
        int wmiP = m / (MFRAG * 16);
        int mrem = m % (MFRAG * 16);
        int mf = mrem >> 4;
        int gg = mrem & 7;
        int j  = (mrem >> 3) & 1;
        baseA[i] = ks * 4 * TSA + ((wmiP * MFRAG + mf) * 8 + gg) * 4 + h * 2 + j;
        int n = rowi[i];
        int wniP = n / (NFRAG * 8);
        int nrem = n % (NFRAG * 8);
        int nf = nrem >> 3;
        int gn = nrem & 7;
        baseB[i] = ks * 4 * TSB + ((wniP * NFRAG + nf) * 8 + gn) * 2 + h;
    }

    float4 ra[2], rb[2];
    #pragma unroll
    for (int i = 0; i < 2; ++i) {
        ra[i] = *(const float4*)(A + (long long)(m0 + rowi[i]) * lda + ki[i]);
        rb[i] = *(const float4*)(W + (long long)(n0 + rowi[i]) * ldw + ki[i]);
    }
    #pragma unroll
    for (int i = 0; i < 2; ++i) {
        sA[baseA[i] + 0 * TSA] = f2tf32(ra[i].x);
        sA[baseA[i] + 1 * TSA] = f2tf32(ra[i].y);
        sA[baseA[i] + 2 * TSA] = f2tf32(ra[i].z);
        sA[baseA[i] + 3 * TSA] = f2tf32(ra[i].w);
        sB[baseB[i] + 0 * TSB] = f2tf32(rb[i].x);
        sB[baseB[i] + 1 * TSB] = f2tf32(rb[i].y);
        sB[baseB[i] + 2 * TSB] = f2tf32(rb[i].z);
        sB[baseB[i] + 3 * TSB] = f2tf32(rb[i].w);
    }
    __syncthreads();

    const int nIter = K / 16;
    for (int it = 0; it < nIter; ++it) {
        int nxt = it + 1;
        if (nxt < nIter) {
            int k0 = nxt * 16;
            #pragma unroll
            for (int i = 0; i < 2; ++i) {
                ra[i] = *(const float4*)(A + (long long)(m0 + rowi[i]) * lda + k0 + ki[i]);
                rb[i] = *(const float4*)(W + (long long)(n0 + rowi[i]) * ldw + k0 + ki[i]);
            }
        }

        // ---- consume current buffer ----
        {
            const uint32_t* ca = sA + (it & 1) * ABUF;
            const uint32_t* cb = sB + (it & 1) * BBUF;
            #pragma unroll
            for (int ks = 0; ks < 2; ++ks) {
                uint32_t af[MFRAG][4];
                #pragma unroll
                for (int mf = 0; mf < MFRAG; ++mf) {
                    const uint4 v = *(const uint4*)(ca + (ks * 4 + t) * TSA
                                    + ((wmi * MFRAG + mf) * 8 + g) * 4);
                    af[mf][0] = v.x; af[mf][1] = v.y; af[mf][2] = v.z; af[mf][3] = v.w;
                }
                uint32_t bf[NFRAG][2];
                #pragma unroll
                for (int nf = 0; nf < NFRAG; ++nf) {
                    const uint2 v = *(const uint2*)(cb + (ks * 4 + t) * TSB
                                    + ((wni * NFRAG + nf) * 8 + g) * 2);
                    bf[nf][0] = v.x; bf[nf][1] = v.y;
                }
                #pragma unroll
                for (int mf = 0; mf < MFRAG; ++mf)
                    #pragma unroll
                    for (int nf = 0; nf < NFRAG; ++nf)
                        mma_tf32(acc[mf][nf], af[mf], bf[nf]);
            }
        }

        if (nxt < nIter) {
            uint32_t* pa = sA + (nxt & 1) * ABUF;
            uint32_t* pb = sB + (nxt & 1) * BBUF;
            #pragma unroll
            for (int i = 0; i < 2; ++i) {
                pa[baseA[i] + 0 * TSA] = f2tf32(ra[i].x);
                pa[baseA[i] + 1 * TSA] = f2tf32(ra[i].y);
                pa[baseA[i] + 2 * TSA] = f2tf32(ra[i].z);
                pa[baseA[i] + 3 * TSA] = f2tf32(ra[i].w);
                pb[baseB[i] + 0 * TSB] = f2tf32(rb[i].x);
                pb[baseB[i] + 1 * TSB] = f2tf32(rb[i].y);
                pb[baseB[i] + 2 * TSB] = f2tf32(rb[i].z);
                pb[baseB[i] + 3 * TSB] = f2tf32(rb[i].w);
            }
        }
        __syncthreads();
    }
}

template<int MFRAG, int NFRAG, int WMG, int WNG>
__device__ __forceinline__ void store_partial_frag(
    float* __restrict__ P, int N, int m0, int n0,
    const float acc[MFRAG][NFRAG][4])
{
    const int lane = threadIdx.x & 31;
    const int warp = threadIdx.x >> 5;
    const int wmi  = warp / WNG;
    const int wni  = warp % WNG;
    const int g    = lane >> 2;
    const int t    = lane & 3;

    #pragma unroll
    for (int mf = 0; mf < MFRAG; ++mf) {
        int mRow = m0 + wmi * MFRAG * 16 + mf * 16 + g;
        #pragma unroll
        for (int nf = 0; nf < NFRAG; ++nf) {
            int nCol = n0 + wni * NFRAG * 8 + nf * 8 + 2 * t;
            *(float2*)&P[(long long)mRow * N + nCol] =
                make_float2(acc[mf][nf][0], acc[mf][nf][1]);
            *(float2*)&P[(long long)(mRow + 8) * N + nCol] =
                make_float2(acc[mf][nf][2], acc[mf][nf][3]);
        }
    }
}

// ---------------------------------------------------------------------------
// GEMM1: 128x128 tiles, 256 thr (WMG=2 x WNG=4 warps of 64x32). TSA=TSB=264.
// ---------------------------------------------------------------------------
#define TS1 264
__global__ __launch_bounds__(256)
void gemm1_tc_kernel(const float* __restrict__ W1)
{
    __shared__ __align__(16) uint32_t sA[2 * 8 * TS1];
    __shared__ __align__(16) uint32_t sB[2 * 8 * TS1];

    const int m0 = blockIdx.y * 128;
    const int n0 = blockIdx.x * 128;
    const int s  = blockIdx.z;
    const int Ks = DIN / SPLIT1;            // 1152

    float acc[4][4][4] = {};
    gemm_frag_phase<4, 4, 2, 4, TS1, TS1>(
        g_glimpse + s * Ks, DIN, W1 + s * Ks, DIN, Ks, m0, n0, sA, sB, acc);
    store_partial_frag<4, 4, 2, 4>(g_part1[s], HG, m0, n0, acc);
}

// reduce1
__global__ void reduce1_kernel(const float* __restrict__ b1)
{
    const int half = BATCH * HG / 2;
    int i0 = (blockIdx.x * blockDim.x + threadIdx.x) * 4;
    if (i0 >= half) return;

    #pragma unroll
    for (int hh = 0; hh < 2; ++hh) {
        int idx = i0 + hh * half;
        float4 v = *(const float4*)&g_part1[0][idx];
        #pragma unroll
        for (int s = 1; s < SPLIT1; ++s) {
            float4 p = *(const float4*)&g_part1[s][idx];
            v.x += p.x; v.y += p.y; v.z += p.z; v.w += p.w;
        }
        int n = idx & (HG - 1);
        float4 bb = *(const float4*)&b1[n];
        v.x = fmaxf(v.x + bb.x, 0.0f);
        v.y = fmaxf(v.y + bb.y, 0.0f);
        v.z = fmaxf(v.z + bb.z, 0.0f);
        v.w = fmaxf(v.w + bb.w, 0.0f);
        *(float4*)&g_h[idx] = v;
    }
}

// ---------------------------------------------------------------------------
// GEMM2: 64x64 tiles, 128 thr (WMG=2 x WNG=2 warps of 32x32). TSA=TSB=136.
// ---------------------------------------------------------------------------
#define TS2 136
__global__ __launch_bounds__(128)
void gemm2_tc_kernel(const float* __restrict__ W3,
                     const float* __restrict__ W4)
{
    __shared__ __align__(16) uint32_t sA[2 * 8 * TS2];
    __shared__ __align__(16) uint32_t sB[2 * 8 * TS2];

    const int m0 = blockIdx.y * 64;
    const int n0 = blockIdx.x * 64;
    const int s  = blockIdx.z;
    const int Ks = HG / SPLIT2;             // 256
    const int k0 = s * Ks;

    float acc[2][4][4] = {};
    gemm_frag_phase<2, 4, 2, 2, TS2, TS2>(
        g_h + k0, HG, W3 + k0, HG, Ks, m0, n0, sA, sB, acc);
    if (s == 0) {
        __syncthreads();
        gemm_frag_phase<2, 4, 2, 2, TS2, TS2>(
            g_hw, HL, W4, HL, HL, m0, n0, sA, sB, acc);
    }
    store_partial_frag<2, 4, 2, 2>(g_part2[s], NOUT, m0, n0, acc);
}

// reduce2
__global__ void reduce2_kernel(const float* __restrict__ b3,
                               const float* __restrict__ b4,
                               float* __restrict__ out)
{
    const int half = BATCH * NOUT / 2;
    int i0 = (blockIdx.x * blockDim.x + threadIdx.x) * 4;
    if (i0 >= half) return;

    #pragma unroll
    for (int hh = 0; hh < 2; ++hh) {
        int idx = i0 + hh * half;
        float4 v = *(const float4*)&g_part2[0][idx];
        #pragma unroll
        for (int s = 1; s < SPLIT2; ++s) {
            float4 p = *(const float4*)&g_part2[s][idx];
            v.x += p.x; v.y += p.y; v.z += p.z; v.w += p.w;
        }
        int n = idx % NOUT;
        float4 b3v = *(const float4*)&b3[n];
        float4 b4v = *(const float4*)&b4[n];
        v.x = fmaxf(v.x + b3v.x + b4v.x, 0.0f);
        v.y = fmaxf(v.y + b3v.y + b4v.y, 0.0f);
        v.z = fmaxf(v.z + b3v.z + b4v.z, 0.0f);
        v.w = fmaxf(v.w + b3v.w + b4v.w, 0.0f);
        *(float4*)&out[idx] = v;
    }
}

// ---------------------------------------------------------------------------
extern "C" void kernel_launch(void* const* d_in, const int* in_sizes, int n_in,
                              void* d_out, int out_size)
{
    const float* x  = (const float*)d_in[0];
    const float* l  = (const float*)d_in[1];
    const float* W1 = (const float*)d_in[2];
    const float* b1 = (const float*)d_in[3];
    const float* W2 = (const float*)d_in[4];
    const float* b2 = (const float*)d_in[5];
    const float* W3 = (const float*)d_in[6];
    const float* b3 = (const float*)d_in[7];
    const float* W4 = (const float*)d_in[8];
    const float* b4 = (const float*)d_in[9];
    float* out = (float*)d_out;

    (void)in_sizes; (void)n_in; (void)out_size;

    // 1) foveation + where (fused)
    foveate2_kernel<<<BATCH * CIN + BATCH * HL / 1024, 256>>>(x, l, W2, b2);

    // 2) h = relu(glimpse @ W1^T + b1): 128x128 frag-packed split-K + reduce
    {
        dim3 grid(HG / 128, BATCH / 128, SPLIT1);   // (8, 4, 8) = 256 blocks
        gemm1_tc_kernel<<<grid, 256>>>(W1);
        int total = BATCH * HG / 8;
        reduce1_kernel<<<(total + 255) / 256, 256>>>(b1);
    }
    // 3) out = relu(h @ W3^T + b3 + hw @ W4^T + b4): 64x64 frag-packed split-K
    {
        dim3 grid(NOUT / 64, BATCH / 64, SPLIT2);   // (18, 8, 4) = 576 blocks
        gemm2_tc_kernel<<<grid, 128>>>(W3, W4);
        int total = BATCH * NOUT / 8;
        reduce2_kernel<<<(total + 255) / 256, 256>>>(b3, b4, out);
    }
}

// round 17
// speedup vs baseline: 1.2244x; 1.2244x over previous
#include <cuda_runtime.h>
#include <cuda_bf16.h>
#include <cstdint>

// Problem constants
#define BATCH 512
#define CIN   3
#define HIMG  256
#define DIN   9216
#define HG    1024
#define HL    128
#define NOUT  1152

#define SPLIT1 8       // GEMM1 K-splits (9216/8 = 1152)
#define SPLIT2 8       // GEMM2 K-splits (1024/8 = 128)

// Scratch
__device__ float g_glimpse[BATCH * DIN];
__device__ float g_h[BATCH * HG];
__device__ float g_hw[BATCH * HL];
__device__ float g_part1[SPLIT1][BATCH * HG];
__device__ float g_part2[SPLIT2][BATCH * NOUT];

// ---------------------------------------------------------------------------
// Foveation (hierarchical) + fused "where" path. (proven R15)
// ---------------------------------------------------------------------------
__global__ __launch_bounds__(256)
void foveate2_kernel(const float* __restrict__ x,
                     const float* __restrict__ l,
                     const float* __restrict__ W2,
                     const float* __restrict__ b2)
{
    __shared__ float p1[64 * 64];

    const int bid = blockIdx.x;
    const int tid = threadIdx.x;

    if (bid >= BATCH * CIN) {
        int base = ((bid - BATCH * CIN) * 256 + tid) * 4;
        int b = base / HL;
        int n = base % HL;
        float l0 = l[2 * b + 0];
        float l1 = l[2 * b + 1];
        float4 bb = *(const float4*)&b2[n];
        float4 w0 = *(const float4*)&W2[2 * n];
        float4 w1 = *(const float4*)&W2[2 * n + 4];
        float4 v;
        v.x = fmaxf(bb.x + l0 * w0.x + l1 * w0.y, 0.0f);
        v.y = fmaxf(bb.y + l0 * w0.z + l1 * w0.w, 0.0f);
        v.z = fmaxf(bb.z + l0 * w1.x + l1 * w1.y, 0.0f);
        v.w = fmaxf(bb.w + l0 * w1.z + l1 * w1.w, 0.0f);
        *(float4*)&g_hw[base] = v;
        return;
    }

    const int b = bid / 3;
    const int c = bid - 3 * b;

    float l0 = l[2 * b + 0];
    float l1 = l[2 * b + 1];
    int fx = (int)floorf(0.5f * ((l0 + 1.0f) * 256.0f));
    int fy = (int)floorf(0.5f * ((l1 + 1.0f) * 256.0f));
    fx = min(max(fx, 0), 256);
    fy = min(max(fy, 0), 256);

    const int y0 = fy - 64;
    const int x0 = fx - 64;

    const float* __restrict__ src = x + ((long long)b * CIN + c) * (HIMG * HIMG);
    float* __restrict__ gout = g_glimpse + (long long)b * DIN + c * 1024;

    #pragma unroll
    for (int i = 0; i < 16; ++i) {
        int q  = tid + 256 * i;
        int qy = q >> 6;
        int qx = q & 63;
        int yb = y0 + 2 * qy;
        int xb = x0 + 2 * qx;

        float v00 = 0.0f, v01 = 0.0f, v10 = 0.0f, v11 = 0.0f;
        bool xi0 = (unsigned)xb < 256u;
        bool xi1 = (unsigned)(xb + 1) < 256u;
        if ((unsigned)yb < 256u) {
            const float* r = src + yb * HIMG;
            if (xi0) v00 = r[xb];
            if (xi1) v01 = r[xb + 1];
        }
        if ((unsigned)(yb + 1) < 256u) {
            const float* r = src + (yb + 1) * HIMG;
            if (xi0) v10 = r[xb];
            if (xi1) v11 = r[xb + 1];
        }
        p1[q] = v00 + v01 + v10 + v11;

        if (qy >= 24 && qy < 40 && qx >= 24 && qx < 40) {
            int i0 = 2 * qy - 48;
            int j0 = 2 * qx - 48;
            gout[i0 * 32 + j0]           = v00;
            gout[i0 * 32 + j0 + 1]       = v01;
            gout[(i0 + 1) * 32 + j0]     = v10;
            gout[(i0 + 1) * 32 + j0 + 1] = v11;
        }
    }
    __syncthreads();

    #pragma unroll
    for (int i = 0; i < 4; ++i) {
        int o  = tid + 256 * i;
        int oi = o >> 5;
        int oj = o & 31;
        gout[3072 + o] = p1[(16 + oi) * 64 + (16 + oj)] * 0.25f;
        float s = p1[(2 * oi) * 64 + 2 * oj]
                + p1[(2 * oi) * 64 + 2 * oj + 1]
                + p1[(2 * oi + 1) * 64 + 2 * oj]
                + p1[(2 * oi + 1) * 64 + 2 * oj + 1];
        gout[6144 + o] = s * 0.0625f;
    }
}

// ---------------------------------------------------------------------------
// TF32 machinery
// ---------------------------------------------------------------------------
__device__ __forceinline__ uint32_t f2tf32(float f) {
    uint32_t u;
    asm("cvt.rna.tf32.f32 %0, %1;" : "=r"(u) : "f"(f));
    return u;
}

__device__ __forceinline__ void mma_tf32(float c[4],
                                         const uint32_t a[4],
                                         const uint32_t b[2]) {
    asm volatile(
        "mma.sync.aligned.m16n8k8.row.col.f32.tf32.tf32.f32 "
        "{%0,%1,%2,%3}, {%4,%5,%6,%7}, {%8,%9}, {%0,%1,%2,%3};"
        : "+f"(c[0]), "+f"(c[1]), "+f"(c[2]), "+f"(c[3])
        : "r"(a[0]), "r"(a[1]), "r"(a[2]), "r"(a[3]),
          "r"(b[0]), "r"(b[1]));
}

// ===========================================================================
// Fragment-packed GEMM, BK=16 (R16 machinery, proven correct)
// ===========================================================================
template<int MFRAG, int NFRAG, int WMG, int WNG, int TSA, int TSB>
__device__ __forceinline__ void gemm_frag_phase(
    const float* __restrict__ A, int lda,
    const float* __restrict__ W, int ldw,
    int K, int m0, int n0,
    uint32_t* __restrict__ sA,
    uint32_t* __restrict__ sB,
    float acc[MFRAG][NFRAG][4])
{
    const int NT   = 32 * WMG * WNG;
    const int tid  = threadIdx.x;
    const int lane = tid & 31;
    const int warp = tid >> 5;
    const int wmi  = warp / WNG;
    const int wni  = warp % WNG;
    const int g    = lane >> 2;
    const int t    = lane & 3;

    const int ABUF = 8 * TSA;
    const int BBUF = 8 * TSB;

    int rowi[2], ki[2], baseA[2], baseB[2];
    #pragma unroll
    for (int i = 0; i < 2; ++i) {
        int idx = tid + NT * i;
        rowi[i] = idx >> 2;
        ki[i]   = (idx & 3) * 4;
        int ks = ki[i] >> 3;
        int h  = (ki[i] >> 2) & 1;
        int m  = rowi[i];
        int wmiP = m / (MFRAG * 16);
        int mrem = m % (MFRAG * 16);
        int mf = mrem >> 4;
        int gg = mrem & 7;
        int j  = (mrem >> 3) & 1;
        baseA[i] = ks * 4 * TSA + ((wmiP * MFRAG + mf) * 8 + gg) * 4 + h * 2 + j;
        int n = rowi[i];
        int wniP = n / (NFRAG * 8);
        int nrem = n % (NFRAG * 8);
        int nf = nrem >> 3;
        int gn = nrem & 7;
        baseB[i] = ks * 4 * TSB + ((wniP * NFRAG + nf) * 8 + gn) * 2 + h;
    }

    float4 ra[2], rb[2];
    #pragma unroll
    for (int i = 0; i < 2; ++i) {
        ra[i] = *(const float4*)(A + (long long)(m0 + rowi[i]) * lda + ki[i]);
        rb[i] = *(const float4*)(W + (long long)(n0 + rowi[i]) * ldw + ki[i]);
    }
    #pragma unroll
    for (int i = 0; i < 2; ++i) {
        sA[baseA[i] + 0 * TSA] = f2tf32(ra[i].x);
        sA[baseA[i] + 1 * TSA] = f2tf32(ra[i].y);
        sA[baseA[i] + 2 * TSA] = f2tf32(ra[i].z);
        sA[baseA[i] + 3 * TSA] = f2tf32(ra[i].w);
        sB[baseB[i] + 0 * TSB] = f2tf32(rb[i].x);
        sB[baseB[i] + 1 * TSB] = f2tf32(rb[i].y);
        sB[baseB[i] + 2 * TSB] = f2tf32(rb[i].z);
        sB[baseB[i] + 3 * TSB] = f2tf32(rb[i].w);
    }
    __syncthreads();

    const int nIter = K / 16;
    for (int it = 0; it < nIter; ++it) {
        int nxt = it + 1;
        if (nxt < nIter) {
            int k0 = nxt * 16;
            #pragma unroll
            for (int i = 0; i < 2; ++i) {
                ra[i] = *(const float4*)(A + (long long)(m0 + rowi[i]) * lda + k0 + ki[i]);
                rb[i] = *(const float4*)(W + (long long)(n0 + rowi[i]) * ldw + k0 + ki[i]);
            }
        }

        {
            const uint32_t* ca = sA + (it & 1) * ABUF;
            const uint32_t* cb = sB + (it & 1) * BBUF;
            #pragma unroll
            for (int ks = 0; ks < 2; ++ks) {
                uint32_t af[MFRAG][4];
                #pragma unroll
                for (int mf = 0; mf < MFRAG; ++mf) {
                    const uint4 v = *(const uint4*)(ca + (ks * 4 + t) * TSA
                                    + ((wmi * MFRAG + mf) * 8 + g) * 4);
                    af[mf][0] = v.x; af[mf][1] = v.y; af[mf][2] = v.z; af[mf][3] = v.w;
                }
                uint32_t bf[NFRAG][2];
                #pragma unroll
                for (int nf = 0; nf < NFRAG; ++nf) {
                    const uint2 v = *(const uint2*)(cb + (ks * 4 + t) * TSB
                                    + ((wni * NFRAG + nf) * 8 + g) * 2);
                    bf[nf][0] = v.x; bf[nf][1] = v.y;
                }
                #pragma unroll
                for (int mf = 0; mf < MFRAG; ++mf)
                    #pragma unroll
                    for (int nf = 0; nf < NFRAG; ++nf)
                        mma_tf32(acc[mf][nf], af[mf], bf[nf]);
            }
        }

        if (nxt < nIter) {
            uint32_t* pa = sA + (nxt & 1) * ABUF;
            uint32_t* pb = sB + (nxt & 1) * BBUF;
            #pragma unroll
            for (int i = 0; i < 2; ++i) {
                pa[baseA[i] + 0 * TSA] = f2tf32(ra[i].x);
                pa[baseA[i] + 1 * TSA] = f2tf32(ra[i].y);
                pa[baseA[i] + 2 * TSA] = f2tf32(ra[i].z);
                pa[baseA[i] + 3 * TSA] = f2tf32(ra[i].w);
                pb[baseB[i] + 0 * TSB] = f2tf32(rb[i].x);
                pb[baseB[i] + 1 * TSB] = f2tf32(rb[i].y);
                pb[baseB[i] + 2 * TSB] = f2tf32(rb[i].z);
                pb[baseB[i] + 3 * TSB] = f2tf32(rb[i].w);
            }
        }
        __syncthreads();
    }
}

template<int MFRAG, int NFRAG, int WMG, int WNG>
__device__ __forceinline__ void store_partial_frag(
    float* __restrict__ P, int N, int m0, int n0,
    const float acc[MFRAG][NFRAG][4])
{
    const int lane = threadIdx.x & 31;
    const int warp = threadIdx.x >> 5;
    const int wmi  = warp / WNG;
    const int wni  = warp % WNG;
    const int g    = lane >> 2;
    const int t    = lane & 3;

    #pragma unroll
    for (int mf = 0; mf < MFRAG; ++mf) {
        int mRow = m0 + wmi * MFRAG * 16 + mf * 16 + g;
        #pragma unroll
        for (int nf = 0; nf < NFRAG; ++nf) {
            int nCol = n0 + wni * NFRAG * 8 + nf * 8 + 2 * t;
            *(float2*)&P[(long long)mRow * N + nCol] =
                make_float2(acc[mf][nf][0], acc[mf][nf][1]);
            *(float2*)&P[(long long)(mRow + 8) * N + nCol] =
                make_float2(acc[mf][nf][2], acc[mf][nf][3]);
        }
    }
}

// ---------------------------------------------------------------------------
// GEMM1: 128x128 tiles, 256 thr; force 2 resident blocks/SM (reg cap 128)
// ---------------------------------------------------------------------------
#define TS1 264
__global__ __launch_bounds__(256, 2)
void gemm1_tc_kernel(const float* __restrict__ W1)
{
    __shared__ __align__(16) uint32_t sA[2 * 8 * TS1];
    __shared__ __align__(16) uint32_t sB[2 * 8 * TS1];

    const int m0 = blockIdx.y * 128;
    const int n0 = blockIdx.x * 128;
    const int s  = blockIdx.z;
    const int Ks = DIN / SPLIT1;            // 1152

    float acc[4][4][4] = {};
    gemm_frag_phase<4, 4, 2, 4, TS1, TS1>(
        g_glimpse + s * Ks, DIN, W1 + s * Ks, DIN, Ks, m0, n0, sA, sB, acc);
    store_partial_frag<4, 4, 2, 4>(g_part1[s], HG, m0, n0, acc);
}

// reduce1
__global__ void reduce1_kernel(const float* __restrict__ b1)
{
    const int half = BATCH * HG / 2;
    int i0 = (blockIdx.x * blockDim.x + threadIdx.x) * 4;
    if (i0 >= half) return;

    #pragma unroll
    for (int hh = 0; hh < 2; ++hh) {
        int idx = i0 + hh * half;
        float4 v = *(const float4*)&g_part1[0][idx];
        #pragma unroll
        for (int s = 1; s < SPLIT1; ++s) {
            float4 p = *(const float4*)&g_part1[s][idx];
            v.x += p.x; v.y += p.y; v.z += p.z; v.w += p.w;
        }
        int n = idx & (HG - 1);
        float4 bb = *(const float4*)&b1[n];
        v.x = fmaxf(v.x + bb.x, 0.0f);
        v.y = fmaxf(v.y + bb.y, 0.0f);
        v.z = fmaxf(v.z + bb.z, 0.0f);
        v.w = fmaxf(v.w + bb.w, 0.0f);
        *(float4*)&g_h[idx] = v;
    }
}

// ---------------------------------------------------------------------------
// GEMM2: 64x64 tiles, 128 thr, SPLIT2=8 (grid 1152 -> ~8 blocks/SM)
// ---------------------------------------------------------------------------
#define TS2 136
__global__ __launch_bounds__(128, 4)
void gemm2_tc_kernel(const float* __restrict__ W3,
                     const float* __restrict__ W4)
{
    __shared__ __align__(16) uint32_t sA[2 * 8 * TS2];
    __shared__ __align__(16) uint32_t sB[2 * 8 * TS2];

    const int m0 = blockIdx.y * 64;
    const int n0 = blockIdx.x * 64;
    const int s  = blockIdx.z;
    const int Ks = HG / SPLIT2;             // 128
    const int k0 = s * Ks;

    float acc[2][4][4] = {};
    gemm_frag_phase<2, 4, 2, 2, TS2, TS2>(
        g_h + k0, HG, W3 + k0, HG, Ks, m0, n0, sA, sB, acc);
    if (s == 0) {
        __syncthreads();
        gemm_frag_phase<2, 4, 2, 2, TS2, TS2>(
            g_hw, HL, W4, HL, HL, m0, n0, sA, sB, acc);
    }
    store_partial_frag<2, 4, 2, 2>(g_part2[s], NOUT, m0, n0, acc);
}

// reduce2
__global__ void reduce2_kernel(const float* __restrict__ b3,
                               const float* __restrict__ b4,
                               float* __restrict__ out)
{
    const int half = BATCH * NOUT / 2;
    int i0 = (blockIdx.x * blockDim.x + threadIdx.x) * 4;
    if (i0 >= half) return;

    #pragma unroll
    for (int hh = 0; hh < 2; ++hh) {
        int idx = i0 + hh * half;
        float4 v = *(const float4*)&g_part2[0][idx];
        #pragma unroll
        for (int s = 1; s < SPLIT2; ++s) {
            float4 p = *(const float4*)&g_part2[s][idx];
            v.x += p.x; v.y += p.y; v.z += p.z; v.w += p.w;
        }
        int n = idx % NOUT;
        float4 b3v = *(const float4*)&b3[n];
        float4 b4v = *(const float4*)&b4[n];
        v.x = fmaxf(v.x + b3v.x + b4v.x, 0.0f);
        v.y = fmaxf(v.y + b3v.y + b4v.y, 0.0f);
        v.z = fmaxf(v.z + b3v.z + b4v.z, 0.0f);
        v.w = fmaxf(v.w + b3v.w + b4v.w, 0.0f);
        *(float4*)&out[idx] = v;
    }
}

// ---------------------------------------------------------------------------
extern "C" void kernel_launch(void* const* d_in, const int* in_sizes, int n_in,
                              void* d_out, int out_size)
{
    const float* x  = (const float*)d_in[0];
    const float* l  = (const float*)d_in[1];
    const float* W1 = (const float*)d_in[2];
    const float* b1 = (const float*)d_in[3];
    const float* W2 = (const float*)d_in[4];
    const float* b2 = (const float*)d_in[5];
    const float* W3 = (const float*)d_in[6];
    const float* b3 = (const float*)d_in[7];
    const float* W4 = (const float*)d_in[8];
    const float* b4 = (const float*)d_in[9];
    float* out = (float*)d_out;

    (void)in_sizes; (void)n_in; (void)out_size;

    // 1) foveation + where (fused)
    foveate2_kernel<<<BATCH * CIN + BATCH * HL / 1024, 256>>>(x, l, W2, b2);

    // 2) h = relu(glimpse @ W1^T + b1)
    {
        dim3 grid(HG / 128, BATCH / 128, SPLIT1);   // (8, 4, 8) = 256 blocks
        gemm1_tc_kernel<<<grid, 256>>>(W1);
        int total = BATCH * HG / 8;
        reduce1_kernel<<<(total + 255) / 256, 256>>>(b1);
    }
    // 3) out = relu(h @ W3^T + b3 + hw @ W4^T + b4)
    {
        dim3 grid(NOUT / 64, BATCH / 64, SPLIT2);   // (18, 8, 8) = 1152 blocks
        gemm2_tc_kernel<<<grid, 128>>>(W3, W4);
        int total = BATCH * NOUT / 8;
        reduce2_kernel<<<(total + 255) / 256, 256>>>(b3, b4, out);
    }
}